// round 9
// baseline (speedup 1.0000x reference)
#include <cuda_runtime.h>
#include <math.h>

#define BB 64
#define FF 240
#define JJ 22
#define NSEG 16
#define NPATH 5
#define BFTOT (BB * FF)
#define FPC 8            // frames per CTA = warps per CTA

__constant__ int c_seg_s[NSEG] = {2,5,8,  1,4,7,  3,6,9,12,  14,17,19,  13,16,18};
__constant__ int c_seg_e[NSEG] = {5,8,11, 4,7,10, 6,9,12,15, 17,19,21,  16,18,20};
__constant__ int c_path_off[NPATH] = {0,3,6,10,13};
__constant__ int c_path_cnt[NPATH] = {3,3,4,3,3};

__device__ float g_pose[BFTOT * 32];
__device__ unsigned char g_flag[BFTOT];

// ---------------- packed f32x2 primitives (sm_103a) ----------------
typedef unsigned long long f2;

__device__ __forceinline__ f2 pk2(float lo, float hi) {
    f2 r; asm("mov.b64 %0, {%1, %2};" : "=l"(r) : "f"(lo), "f"(hi)); return r;
}
__device__ __forceinline__ void upk2(float& lo, float& hi, f2 v) {
    asm("mov.b64 {%0, %1}, %2;" : "=f"(lo), "=f"(hi) : "l"(v));
}
__device__ __forceinline__ f2 bc(float v) {
    unsigned u = __float_as_uint(v);
    return ((f2)u << 32) | (f2)u;
}
__device__ __forceinline__ f2 f2fma(f2 a, f2 b, f2 c) {
    f2 r; asm("fma.rn.f32x2 %0, %1, %2, %3;" : "=l"(r) : "l"(a), "l"(b), "l"(c)); return r;
}
__device__ __forceinline__ f2 f2mul(f2 a, f2 b) {
    f2 r; asm("mul.rn.f32x2 %0, %1, %2;" : "=l"(r) : "l"(a), "l"(b)); return r;
}
__device__ __forceinline__ f2 f2add(f2 a, f2 b) {
    f2 r; asm("add.rn.f32x2 %0, %1, %2;" : "=l"(r) : "l"(a), "l"(b)); return r;
}
// native packed sub: 1 issue-slot vs 3 for neg(2xLOP)+add
__device__ __forceinline__ f2 f2sub(f2 a, f2 b) {
    f2 r; asm("sub.rn.f32x2 %0, %1, %2;" : "=l"(r) : "l"(a), "l"(b)); return r;
}
__device__ __forceinline__ f2 f2abs(f2 a) { return a & 0x7FFFFFFF7FFFFFFFULL; }

struct V3p { f2 x, y, z; };

__device__ __forceinline__ V3p p_sub(V3p a, V3p b) {
    return { f2sub(a.x,b.x), f2sub(a.y,b.y), f2sub(a.z,b.z) };
}
// cross via 2*mul + sub per component (3 slots vs 4 with neg+fma)
__device__ __forceinline__ V3p p_cross(V3p a, V3p b) {
    return { f2sub(f2mul(a.y, b.z), f2mul(a.z, b.y)),
             f2sub(f2mul(a.z, b.x), f2mul(a.x, b.z)),
             f2sub(f2mul(a.x, b.y), f2mul(a.y, b.x)) };
}
__device__ __forceinline__ f2 p_dot(V3p a, V3p b) {
    return f2fma(a.z, b.z, f2fma(a.y, b.y, f2mul(a.x, b.x)));
}

// guarded packed reciprocal-sqrt of squared norms: ss==0 -> finite big (so
// d = g * r_i * r_j stays finite; g == 0 whenever a cross is the 0-vector)
__device__ __forceinline__ f2 grsqrt2(f2 ss) {
    float l, h; upk2(l, h, ss);
    float rl = fminf(rsqrtf(l), 1e30f);
    float rh = fminf(rsqrtf(h), 1e30f);
    return pk2(rl, rh);
}

// packed asin with built-in saturation: for |x|>=1 returns sign(x)*pi/2
// (replaces the reference's clip(-1,1)+asin). No predicates, no selects.
__device__ __forceinline__ f2 asin2(f2 x) {
    f2 ax = f2abs(x);
    f2 a2 = f2mul(ax, ax);
    f2 w  = f2fma(ax, bc(-0.5f), bc(0.5f));      // (1-a)/2
    float a2l, a2h, wl, wh, al, ah;
    upk2(a2l, a2h, a2); upk2(wl, wh, w); upk2(al, ah, ax);
    float zl = fminf(a2l, wl), zh = fminf(a2h, wh);   // z<0 iff a>1
    float sl = fmaxf(zl * rsqrtf(zl), 0.0f);          // sqrt(z), NaN/neg -> 0
    float sh = fmaxf(zh * rsqrtf(zh), 0.0f);
    float bl = fminf(fmaxf(fmaf(al, 1e30f, -5e29f), 0.0f), 1.0f);   // a>0.5 ? 1 : 0
    float bh = fminf(fmaxf(fmaf(ah, 1e30f, -5e29f), 0.0f), 1.0f);
    f2 z = pk2(zl, zh);
    f2 s = pk2(sl, sh);
    f2 bg = pk2(bl, bh);
    f2 p = bc(4.2163199048e-2f);
    p = f2fma(p, z, bc(2.4181311049e-2f));
    p = f2fma(p, z, bc(4.5470025998e-2f));
    p = f2fma(p, z, bc(7.4953002686e-2f));
    p = f2fma(p, z, bc(1.6666752422e-1f));
    f2 t = f2fma(f2mul(s, z), p, s);              // asin(s), >= 0
    f2 v = f2fma(t, bc(-3.0f), bc(1.5707963267948966f));   // pi/2 - 3t
    f2 r = f2fma(bg, v, t);                       // big ? pi/2-2t : t
    return r | (x & 0x8000000080000000ULL);       // apply sign of x
}

__device__ __forceinline__ float wmaxf(float v) {
    #pragma unroll
    for (int o = 16; o; o >>= 1) v = fmaxf(v, __shfl_xor_sync(0xffffffffu, v, o));
    return v;
}
__device__ __forceinline__ float wminf(float v) {
    #pragma unroll
    for (int o = 16; o; o >>= 1) v = fminf(v, __shfl_xor_sync(0xffffffffu, v, o));
    return v;
}

// one WARP per frame, 8 frames per CTA; each lane packs 2 GLI pairs per step.
// Launched twice on half frame-ranges (frame0 param) so ncu -s 5 lands on it.
__global__ void __launch_bounds__(FPC * 32) gli_kernel(
    const float* __restrict__ motion1,
    const float* __restrict__ motion2,
    int frame0)
{
    const int w    = threadIdx.x >> 5;
    const int lane = threadIdx.x & 31;
    const int bf   = frame0 + blockIdx.x * FPC + w;

    __shared__ float2 jnt[FPC][2][33];
    __shared__ float  gbuf[FPC][256];

    {
        const float2* p1 = (const float2*)motion1 + (size_t)bf * 33;
        const float2* p2 = (const float2*)motion2 + (size_t)bf * 33;
        jnt[w][0][lane] = p1[lane];
        jnt[w][1][lane] = p2[lane];
        if (lane == 0) {           // element 32 (joint 21 y,z)
            jnt[w][0][32] = p1[32];
            jnt[w][1][32] = p2[32];
        }
    }
    __syncwarp();

    const float* m1s = (const float*)jnt[w][0];
    const float* m2s = (const float*)jnt[w][1];

    // ---- xz bbox overlap flag via warp shuffle reduction ----
    {
        bool ok = lane < JJ;
        float x1 = ok ? m1s[3*lane]     :  1e30f;
        float z1 = ok ? m1s[3*lane + 2] :  1e30f;
        float x2 = ok ? m2s[3*lane]     :  1e30f;
        float z2 = ok ? m2s[3*lane + 2] :  1e30f;
        float X1 = ok ? x1 : -1e30f, Z1 = ok ? z1 : -1e30f;
        float X2 = ok ? x2 : -1e30f, Z2 = ok ? z2 : -1e30f;
        float nx1 = wminf(x1), xx1 = wmaxf(X1);
        float nz1 = wminf(z1), xz1 = wmaxf(Z1);
        float nx2 = wminf(x2), xx2 = wmaxf(X2);
        float nz2 = wminf(z2), xz2 = wmaxf(Z2);
        if (lane == 0) {
            bool fl = (xx1 >= nx2) && (xx2 >= nx1) && (xz1 >= nz2) && (xz2 >= nz1);
            g_flag[bf] = fl ? 1 : 0;
        }
    }

    // ---- packed GLI: lane covers n = lane&15; m pairs (2i+h, 2i+h+8) ----
    const int n = lane & 15;
    const int h = lane >> 4;
    const int js2 = 3 * c_seg_s[n], je2 = 3 * c_seg_e[n];
    const V3p s2p = { bc(m2s[js2]), bc(m2s[js2+1]), bc(m2s[js2+2]) };
    const V3p e2p = { bc(m2s[je2]), bc(m2s[je2+1]), bc(m2s[je2+2]) };
    const float INV4PI = 0.07957747154594767f;

    #pragma unroll 2
    for (int i = 0; i < 4; ++i) {
        const int mlo = 2 * i + h;
        const int mhi = mlo + 8;
        const int sa = 3 * c_seg_s[mlo], sb = 3 * c_seg_s[mhi];
        const int ea = 3 * c_seg_e[mlo], eb = 3 * c_seg_e[mhi];
        V3p s1p = { pk2(m1s[sa], m1s[sb]), pk2(m1s[sa+1], m1s[sb+1]), pk2(m1s[sa+2], m1s[sb+2]) };
        V3p e1p = { pk2(m1s[ea], m1s[eb]), pk2(m1s[ea+1], m1s[eb+1]), pk2(m1s[ea+2], m1s[eb+2]) };

        V3p r13 = p_sub(s2p, s1p);
        V3p r14 = p_sub(e2p, s1p);
        V3p r12 = p_sub(e1p, s1p);

        // normals: c0 = A, c1 = B, c3 = -C, c2 = B - A - C (never materialized)
        V3p A  = p_cross(r13, r14);
        V3p Bv = p_cross(r12, r14);
        V3p Cv = p_cross(r12, r13);

        // Gram matrix of {A, B, C}
        f2 gAA = p_dot(A, A);
        f2 gBB = p_dot(Bv, Bv);
        f2 gCC = p_dot(Cv, Cv);
        f2 gAB = p_dot(A, Bv);
        f2 gBC = p_dot(Bv, Cv);
        f2 gCA = p_dot(Cv, A);

        // ss2 = |B-A-C|^2 = AA+BB+CC - 2AB - 2BC + 2CA
        f2 ss2 = f2add(f2add(gAA, gBB), gCC);
        ss2 = f2fma(gAB, bc(-2.0f), ss2);
        ss2 = f2fma(gBC, bc(-2.0f), ss2);
        ss2 = f2fma(gCA, bc( 2.0f), ss2);

        f2 n12 = f2sub(f2sub(gBB, gAB), gBC);   // B·c2
        f2 n23 = f2sub(f2sub(gBC, gCA), gCC);   // c2·C  (= -true d23 numerator)

        f2 r0 = grsqrt2(gAA);
        f2 r1 = grsqrt2(gBB);
        f2 r2 = grsqrt2(ss2);
        f2 r3 = grsqrt2(gCC);

        f2 d01 = f2mul(f2mul(gAB, r0), r1);
        f2 d12 = f2mul(f2mul(n12, r1), r2);
        f2 d23 = f2mul(f2mul(n23, r2), r3);     // = -true d23
        f2 d30 = f2mul(f2mul(gCA, r3), r0);     // = -true d30
        f2 tot = f2sub(f2add(asin2(d01), asin2(d12)),
                       f2add(asin2(d23), asin2(d30)));

        // ref sign = (r34 x r12)·r13 = (C-B)·r13 = -B·r13  (C·r13 == 0 exactly)
        f2 sgB = p_dot(Bv, r13);                // = -sign

        float sgl, sgh, totl, toth;
        upk2(sgl, sgh, sgB); upk2(totl, toth, tot);
        float outl = totl * ((sgl >= 0.0f) ? -INV4PI : INV4PI);
        float outh = toth * ((sgh >= 0.0f) ? -INV4PI : INV4PI);
        gbuf[w][mlo * 16 + n] = outl;
        gbuf[w][mhi * 16 + n] = outh;
    }
    __syncwarp();

    if (lane < 25) {
        const int i = lane / 5;
        const int j = lane % 5;
        const int mo = c_path_off[i], mc = c_path_cnt[i];
        const int no = c_path_off[j], nc = c_path_cnt[j];
        float s = 0.0f;
        for (int m = mo; m < mo + mc; ++m)
            for (int nn = no; nn < no + nc; ++nn)
                s += gbuf[w][m * 16 + nn];
        g_pose[(size_t)bf * 32 + lane] = s;
    }
}

// one WARP per output element in [out0, out1): maximum parallelism
__global__ void __launch_bounds__(256) vel_kernel(float* __restrict__ out,
                                                  int out0, int out1)
{
    const int gw   = out0 + ((blockIdx.x * blockDim.x + threadIdx.x) >> 5);
    const int lane = threadIdx.x & 31;
    if (gw >= out1) return;

    const int b = gw / (FF - 1);
    const int f = gw % (FF - 1);
    const int bf = b * FF + f;
    const unsigned char* fl = &g_flag[b * FF];

    unsigned char fm1 = (f > 0) ? fl[f - 1] : 0;
    unsigned char f0  = fl[f];
    unsigned char f1  = fl[f + 1];
    unsigned char f2_ = (f + 2 < FF) ? fl[f + 2] : 0;
    float m0 = (fm1 | f0 | f1) ? 1.0f : 0.0f;
    float m1 = (f0 | f1 | f2_) ? 1.0f : 0.0f;

    float d = 0.0f;
    if (lane < 25) {
        float p0 = g_pose[(size_t)bf * 32 + lane];
        float p1 = g_pose[(size_t)(bf + 1) * 32 + lane];
        d = fabsf(p1 * m1 - p0 * m0);
    }
    d = wmaxf(d);
    if (lane == 0) out[gw] = d;
}

extern "C" void kernel_launch(void* const* d_in, const int* in_sizes, int n_in,
                              void* d_out, int out_size)
{
    const float* motion1 = (const float*)d_in[0];
    const float* motion2 = (const float*)d_in[1];
    float* out = (float*)d_out;

    // 4 launches/call so ncu's "-s 5 -c 1" lands on gli (launch #6), not vel
    const int halfF = BFTOT / 2;                     // 7680 frames
    gli_kernel<<<halfF / FPC, FPC * 32>>>(motion1, motion2, 0);
    gli_kernel<<<halfF / FPC, FPC * 32>>>(motion1, motion2, halfF);

    const int total = BB * (FF - 1);                 // 15296 outputs
    const int halfO = total / 2;                     // 7648 (= 32 full batches)
    vel_kernel<<<(halfO * 32 + 255) / 256, 256>>>(out, 0, halfO);
    vel_kernel<<<((total - halfO) * 32 + 255) / 256, 256>>>(out, halfO, total);
}

// round 10
// speedup vs baseline: 1.1755x; 1.1755x over previous
#include <cuda_runtime.h>
#include <math.h>

#define BB 64
#define FF 240
#define JJ 22
#define NSEG 16
#define NPATH 5
#define BFTOT (BB * FF)
#define FPC 8            // frames per CTA = warps per CTA

__constant__ int c_seg_s[NSEG] = {2,5,8,  1,4,7,  3,6,9,12,  14,17,19,  13,16,18};
__constant__ int c_seg_e[NSEG] = {5,8,11, 4,7,10, 6,9,12,15, 17,19,21,  16,18,20};
__constant__ int c_path_off[NPATH] = {0,3,6,10,13};
__constant__ int c_path_cnt[NPATH] = {3,3,4,3,3};

__device__ float g_pose[BFTOT * 32];
__device__ unsigned char g_flag[BFTOT];

// ---------------- packed f32x2 primitives (sm_103a) ----------------
typedef unsigned long long f2;

__device__ __forceinline__ f2 pk2(float lo, float hi) {
    f2 r; asm("mov.b64 %0, {%1, %2};" : "=l"(r) : "f"(lo), "f"(hi)); return r;
}
__device__ __forceinline__ void upk2(float& lo, float& hi, f2 v) {
    asm("mov.b64 {%0, %1}, %2;" : "=f"(lo), "=f"(hi) : "l"(v));
}
__device__ __forceinline__ f2 bc(float v) {
    unsigned u = __float_as_uint(v);
    return ((f2)u << 32) | (f2)u;
}
__device__ __forceinline__ f2 f2fma(f2 a, f2 b, f2 c) {
    f2 r; asm("fma.rn.f32x2 %0, %1, %2, %3;" : "=l"(r) : "l"(a), "l"(b), "l"(c)); return r;
}
__device__ __forceinline__ f2 f2mul(f2 a, f2 b) {
    f2 r; asm("mul.rn.f32x2 %0, %1, %2;" : "=l"(r) : "l"(a), "l"(b)); return r;
}
__device__ __forceinline__ f2 f2add(f2 a, f2 b) {
    f2 r; asm("add.rn.f32x2 %0, %1, %2;" : "=l"(r) : "l"(a), "l"(b)); return r;
}
// native packed sub: 1 issue-slot
__device__ __forceinline__ f2 f2sub(f2 a, f2 b) {
    f2 r; asm("sub.rn.f32x2 %0, %1, %2;" : "=l"(r) : "l"(a), "l"(b)); return r;
}
__device__ __forceinline__ f2 f2abs(f2 a) { return a & 0x7FFFFFFF7FFFFFFFULL; }

struct V3p { f2 x, y, z; };

__device__ __forceinline__ V3p p_sub(V3p a, V3p b) {
    return { f2sub(a.x,b.x), f2sub(a.y,b.y), f2sub(a.z,b.z) };
}
// cross via 2*mul + sub per component (3 slots)
__device__ __forceinline__ V3p p_cross(V3p a, V3p b) {
    return { f2sub(f2mul(a.y, b.z), f2mul(a.z, b.y)),
             f2sub(f2mul(a.z, b.x), f2mul(a.x, b.z)),
             f2sub(f2mul(a.x, b.y), f2mul(a.y, b.x)) };
}
__device__ __forceinline__ f2 p_dot(V3p a, V3p b) {
    return f2fma(a.z, b.z, f2fma(a.y, b.y, f2mul(a.x, b.x)));
}

// guarded packed reciprocal-sqrt of squared norms: ss==0 -> finite big (so
// d = g * r_i * r_j stays finite; g == 0 whenever a cross is the 0-vector)
__device__ __forceinline__ f2 grsqrt2(f2 ss) {
    float l, h; upk2(l, h, ss);
    float rl = fminf(rsqrtf(l), 1e30f);
    float rh = fminf(rsqrtf(h), 1e30f);
    return pk2(rl, rh);
}

// packed asin with built-in saturation: for |x|>=1 returns sign(x)*pi/2
// (replaces the reference's clip(-1,1)+asin). No predicates, no selects.
__device__ __forceinline__ f2 asin2(f2 x) {
    f2 ax = f2abs(x);
    f2 a2 = f2mul(ax, ax);
    f2 w  = f2fma(ax, bc(-0.5f), bc(0.5f));      // (1-a)/2
    float a2l, a2h, wl, wh, al, ah;
    upk2(a2l, a2h, a2); upk2(wl, wh, w); upk2(al, ah, ax);
    float zl = fminf(a2l, wl), zh = fminf(a2h, wh);   // z<0 iff a>1
    float sl = fmaxf(zl * rsqrtf(zl), 0.0f);          // sqrt(z), NaN/neg -> 0
    float sh = fmaxf(zh * rsqrtf(zh), 0.0f);
    float bl = fminf(fmaxf(fmaf(al, 1e30f, -5e29f), 0.0f), 1.0f);   // a>0.5 ? 1 : 0
    float bh = fminf(fmaxf(fmaf(ah, 1e30f, -5e29f), 0.0f), 1.0f);
    f2 z = pk2(zl, zh);
    f2 s = pk2(sl, sh);
    f2 bg = pk2(bl, bh);
    f2 p = bc(4.2163199048e-2f);
    p = f2fma(p, z, bc(2.4181311049e-2f));
    p = f2fma(p, z, bc(4.5470025998e-2f));
    p = f2fma(p, z, bc(7.4953002686e-2f));
    p = f2fma(p, z, bc(1.6666752422e-1f));
    f2 t = f2fma(f2mul(s, z), p, s);              // asin(s), >= 0
    f2 v = f2fma(t, bc(-3.0f), bc(1.5707963267948966f));   // pi/2 - 3t
    f2 r = f2fma(bg, v, t);                       // big ? pi/2-2t : t
    return r | (x & 0x8000000080000000ULL);       // apply sign of x
}

__device__ __forceinline__ float wmaxf(float v) {
    #pragma unroll
    for (int o = 16; o; o >>= 1) v = fmaxf(v, __shfl_xor_sync(0xffffffffu, v, o));
    return v;
}
__device__ __forceinline__ float wminf(float v) {
    #pragma unroll
    for (int o = 16; o; o >>= 1) v = fminf(v, __shfl_xor_sync(0xffffffffu, v, o));
    return v;
}

// one WARP per frame, 8 frames per CTA; each lane packs 2 GLI pairs per step
__global__ void __launch_bounds__(FPC * 32) gli_kernel(
    const float* __restrict__ motion1,
    const float* __restrict__ motion2)
{
    const int w    = threadIdx.x >> 5;
    const int lane = threadIdx.x & 31;
    const int bf   = blockIdx.x * FPC + w;

    __shared__ float2 jnt[FPC][2][33];
    __shared__ float  gbuf[FPC][256];

    {
        const float2* p1 = (const float2*)motion1 + (size_t)bf * 33;
        const float2* p2 = (const float2*)motion2 + (size_t)bf * 33;
        jnt[w][0][lane] = p1[lane];
        jnt[w][1][lane] = p2[lane];
        if (lane == 0) {           // element 32 (joint 21 y,z)
            jnt[w][0][32] = p1[32];
            jnt[w][1][32] = p2[32];
        }
    }
    __syncwarp();

    const float* m1s = (const float*)jnt[w][0];
    const float* m2s = (const float*)jnt[w][1];

    // ---- xz bbox overlap flag via warp shuffle reduction ----
    {
        bool ok = lane < JJ;
        float x1 = ok ? m1s[3*lane]     :  1e30f;
        float z1 = ok ? m1s[3*lane + 2] :  1e30f;
        float x2 = ok ? m2s[3*lane]     :  1e30f;
        float z2 = ok ? m2s[3*lane + 2] :  1e30f;
        float X1 = ok ? x1 : -1e30f, Z1 = ok ? z1 : -1e30f;
        float X2 = ok ? x2 : -1e30f, Z2 = ok ? z2 : -1e30f;
        float nx1 = wminf(x1), xx1 = wmaxf(X1);
        float nz1 = wminf(z1), xz1 = wmaxf(Z1);
        float nx2 = wminf(x2), xx2 = wmaxf(X2);
        float nz2 = wminf(z2), xz2 = wmaxf(Z2);
        if (lane == 0) {
            bool fl = (xx1 >= nx2) && (xx2 >= nx1) && (xz1 >= nz2) && (xz2 >= nz1);
            g_flag[bf] = fl ? 1 : 0;
        }
    }

    // ---- packed GLI: lane covers n = lane&15; m pairs (2i+h, 2i+h+8) ----
    const int n = lane & 15;
    const int h = lane >> 4;
    const int js2 = 3 * c_seg_s[n], je2 = 3 * c_seg_e[n];
    const V3p s2p = { bc(m2s[js2]), bc(m2s[js2+1]), bc(m2s[js2+2]) };
    const V3p e2p = { bc(m2s[je2]), bc(m2s[je2+1]), bc(m2s[je2+2]) };
    const float INV4PI = 0.07957747154594767f;

    #pragma unroll 2
    for (int i = 0; i < 4; ++i) {
        const int mlo = 2 * i + h;
        const int mhi = mlo + 8;
        const int sa = 3 * c_seg_s[mlo], sb = 3 * c_seg_s[mhi];
        const int ea = 3 * c_seg_e[mlo], eb = 3 * c_seg_e[mhi];
        V3p s1p = { pk2(m1s[sa], m1s[sb]), pk2(m1s[sa+1], m1s[sb+1]), pk2(m1s[sa+2], m1s[sb+2]) };
        V3p e1p = { pk2(m1s[ea], m1s[eb]), pk2(m1s[ea+1], m1s[eb+1]), pk2(m1s[ea+2], m1s[eb+2]) };

        V3p r13 = p_sub(s2p, s1p);
        V3p r14 = p_sub(e2p, s1p);
        V3p r12 = p_sub(e1p, s1p);

        // normals: c0 = A, c1 = B, c3 = -C, c2 = B - A - C (never materialized)
        V3p A  = p_cross(r13, r14);
        V3p Bv = p_cross(r12, r14);
        V3p Cv = p_cross(r12, r13);

        // Gram matrix of {A, B, C}
        f2 gAA = p_dot(A, A);
        f2 gBB = p_dot(Bv, Bv);
        f2 gCC = p_dot(Cv, Cv);
        f2 gAB = p_dot(A, Bv);
        f2 gBC = p_dot(Bv, Cv);
        f2 gCA = p_dot(Cv, A);

        // ss2 = |B-A-C|^2 = AA+BB+CC - 2AB - 2BC + 2CA
        f2 ss2 = f2add(f2add(gAA, gBB), gCC);
        ss2 = f2fma(gAB, bc(-2.0f), ss2);
        ss2 = f2fma(gBC, bc(-2.0f), ss2);
        ss2 = f2fma(gCA, bc( 2.0f), ss2);

        f2 n12 = f2sub(f2sub(gBB, gAB), gBC);   // B·c2
        f2 n23 = f2sub(f2sub(gBC, gCA), gCC);   // c2·C  (= -true d23 numerator)

        f2 r0 = grsqrt2(gAA);
        f2 r1 = grsqrt2(gBB);
        f2 r2 = grsqrt2(ss2);
        f2 r3 = grsqrt2(gCC);

        f2 d01 = f2mul(f2mul(gAB, r0), r1);
        f2 d12 = f2mul(f2mul(n12, r1), r2);
        f2 d23 = f2mul(f2mul(n23, r2), r3);     // = -true d23
        f2 d30 = f2mul(f2mul(gCA, r3), r0);     // = -true d30
        f2 tot = f2sub(f2add(asin2(d01), asin2(d12)),
                       f2add(asin2(d23), asin2(d30)));
        tot = f2mul(tot, bc(INV4PI));           // packed scale once

        // ref sign = (r34 x r12)·r13 = (C-B)·r13 = -B·r13  (C·r13 == 0 exactly)
        f2 sgB = p_dot(Bv, r13);                // = -sign

        float sgl, sgh, totl, toth;
        upk2(sgl, sgh, sgB); upk2(totl, toth, tot);
        gbuf[w][mlo * 16 + n] = (sgl >= 0.0f) ? -totl : totl;
        gbuf[w][mhi * 16 + n] = (sgh >= 0.0f) ? -toth : toth;
    }
    __syncwarp();

    if (lane < 25) {
        const int i = lane / 5;
        const int j = lane % 5;
        const int mo = c_path_off[i], mc = c_path_cnt[i];
        const int no = c_path_off[j], nc = c_path_cnt[j];
        float s = 0.0f;
        for (int m = mo; m < mo + mc; ++m)
            for (int nn = no; nn < no + nc; ++nn)
                s += gbuf[w][m * 16 + nn];
        g_pose[(size_t)bf * 32 + lane] = s;
    }
}

// one WARP per output element [B, F-1]: maximum parallelism (1912 CTAs)
__global__ void __launch_bounds__(256) vel_kernel(float* __restrict__ out)
{
    const int gw   = (blockIdx.x * blockDim.x + threadIdx.x) >> 5;
    const int lane = threadIdx.x & 31;
    const int total = BB * (FF - 1);
    if (gw >= total) return;

    const int b = gw / (FF - 1);
    const int f = gw % (FF - 1);
    const int bf = b * FF + f;
    const unsigned char* fl = &g_flag[b * FF];

    unsigned char fm1 = (f > 0) ? fl[f - 1] : 0;
    unsigned char f0  = fl[f];
    unsigned char f1  = fl[f + 1];
    unsigned char f2_ = (f + 2 < FF) ? fl[f + 2] : 0;
    float m0 = (fm1 | f0 | f1) ? 1.0f : 0.0f;
    float m1 = (f0 | f1 | f2_) ? 1.0f : 0.0f;

    float d = 0.0f;
    if (lane < 25) {
        float p0 = g_pose[(size_t)bf * 32 + lane];
        float p1 = g_pose[(size_t)(bf + 1) * 32 + lane];
        d = fabsf(p1 * m1 - p0 * m0);
    }
    d = wmaxf(d);
    if (lane == 0) out[gw] = d;
}

extern "C" void kernel_launch(void* const* d_in, const int* in_sizes, int n_in,
                              void* d_out, int out_size)
{
    const float* motion1 = (const float*)d_in[0];
    const float* motion2 = (const float*)d_in[1];
    float* out = (float*)d_out;

    gli_kernel<<<BFTOT / FPC, FPC * 32>>>(motion1, motion2);

    const int nwarps = BB * (FF - 1);
    vel_kernel<<<(nwarps * 32 + 255) / 256, 256>>>(out);
}